// round 6
// baseline (speedup 1.0000x reference)
#include <cuda_runtime.h>
#include <cuda_bf16.h>
#include <cstdint>

typedef unsigned long long ull;

// Problem constants
#define BB   256
#define TT   512
#define DD   300
#define HH   128
#define G4   512          // 4*H
#define CC   6

// ---------------- scratch (device globals: allocation-free) ----------------
__device__ float g_gx[(size_t)TT * BB * G4];   // [t][b][g]
__device__ float g_h[BB * HH];                 // final hidden

// ---------------- f32x2 helpers ----------------
__device__ __forceinline__ ull fma2(ull a, ull b, ull c) {
    ull d;
    asm("fma.rn.f32x2 %0, %1, %2, %3;" : "=l"(d) : "l"(a), "l"(b), "l"(c));
    return d;
}
__device__ __forceinline__ ull pack2(float lo, float hi) {
    ull r;
    asm("mov.b64 %0, {%1, %2};" : "=l"(r) : "f"(lo), "f"(hi));
    return r;
}
__device__ __forceinline__ float2 unpk(ull v) {
    float2 r;
    asm("mov.b64 {%0, %1}, %2;" : "=f"(r.x), "=f"(r.y) : "l"(v));
    return r;
}
__device__ __forceinline__ float sum2(ull v) {
    float2 r = unpk(v);
    return r.x + r.y;
}
__device__ __forceinline__ float sigf(float x) {
    return 1.f / (1.f + __expf(-x));
}
__device__ __forceinline__ float tanhf_fast(float x) {
    float e = __expf(-2.f * fabsf(x));
    float r = (1.f - e) / (1.f + e);
    return copysignf(r, x);
}

// ======================================================================
// Kernel 1: gx = x @ W_ih^T + b_ih + b_hh
// 128x128 tile, 256 threads, 8x8 micro-tile split 4+4, FFMA2 inner loop.
// acc2[i][jp]: lanes = (col 2jp, col 2jp+1) of the j-fragment.
// ======================================================================
#define K1_STRIDE 132

__global__ void __launch_bounds__(256, 2) gx_kernel(
    const float* __restrict__ x,
    const float* __restrict__ W_ih,
    const float* __restrict__ b_ih,
    const float* __restrict__ b_hh)
{
    __shared__ float As[8 * K1_STRIDE];
    __shared__ float Bs[8 * K1_STRIDE];

    const int tid = threadIdx.x;
    const int m0  = blockIdx.x * 128;
    const int n0  = blockIdx.y * 128;
    const int t   = m0 >> 8;
    const int b0  = m0 & 255;

    const int lrow = tid >> 1;
    const int lkq  = tid & 1;

    const float* aptr = x    + (size_t)(b0 + lrow) * ((size_t)TT * DD) + (size_t)t * DD;
    const float* bptr = W_ih + (size_t)(n0 + lrow) * DD;

    const int ty = tid >> 4;
    const int tx = tid & 15;

    ull acc2[8][4];
#pragma unroll
    for (int i = 0; i < 8; ++i)
#pragma unroll
        for (int j = 0; j < 4; ++j) acc2[i][j] = 0ULL;

    float4 ra, rb;
    {
        int kk = lkq * 4;
        ra = *reinterpret_cast<const float4*>(aptr + kk);
        rb = *reinterpret_cast<const float4*>(bptr + kk);
    }

    for (int k0 = 0; k0 < DD; k0 += 8) {
        const int kb = lkq * 4;
        As[(kb+0)*K1_STRIDE + lrow] = ra.x;
        As[(kb+1)*K1_STRIDE + lrow] = ra.y;
        As[(kb+2)*K1_STRIDE + lrow] = ra.z;
        As[(kb+3)*K1_STRIDE + lrow] = ra.w;
        Bs[(kb+0)*K1_STRIDE + lrow] = rb.x;
        Bs[(kb+1)*K1_STRIDE + lrow] = rb.y;
        Bs[(kb+2)*K1_STRIDE + lrow] = rb.z;
        Bs[(kb+3)*K1_STRIDE + lrow] = rb.w;
        __syncthreads();

        int kn = k0 + 8 + lkq * 4;
        if (k0 + 8 < DD) {
            ra = (kn < DD) ? *reinterpret_cast<const float4*>(aptr + kn) : make_float4(0,0,0,0);
            rb = (kn < DD) ? *reinterpret_cast<const float4*>(bptr + kn) : make_float4(0,0,0,0);
        }

#pragma unroll
        for (int k = 0; k < 8; ++k) {
            float av[8];
            *reinterpret_cast<float4*>(&av[0]) = *reinterpret_cast<const float4*>(&As[k*K1_STRIDE + ty*4]);
            *reinterpret_cast<float4*>(&av[4]) = *reinterpret_cast<const float4*>(&As[k*K1_STRIDE + 64 + ty*4]);
            ulonglong2 b01 = *reinterpret_cast<const ulonglong2*>(&Bs[k*K1_STRIDE + tx*4]);
            ulonglong2 b23 = *reinterpret_cast<const ulonglong2*>(&Bs[k*K1_STRIDE + 64 + tx*4]);
#pragma unroll
            for (int i = 0; i < 8; ++i) {
                ull as = pack2(av[i], av[i]);
                acc2[i][0] = fma2(as, b01.x, acc2[i][0]);
                acc2[i][1] = fma2(as, b01.y, acc2[i][1]);
                acc2[i][2] = fma2(as, b23.x, acc2[i][2]);
                acc2[i][3] = fma2(as, b23.y, acc2[i][3]);
            }
        }
        __syncthreads();
    }

    float bias[8];
#pragma unroll
    for (int j = 0; j < 4; ++j) {
        bias[j]     = b_ih[n0 + tx*4 + j]      + b_hh[n0 + tx*4 + j];
        bias[4 + j] = b_ih[n0 + 64 + tx*4 + j] + b_hh[n0 + 64 + tx*4 + j];
    }
#pragma unroll
    for (int half = 0; half < 2; ++half) {
#pragma unroll
        for (int i = 0; i < 4; ++i) {
            int m = m0 + half * 64 + ty*4 + i;
            int ii = half * 4 + i;
            float2 p0 = unpk(acc2[ii][0]);
            float2 p1 = unpk(acc2[ii][1]);
            float2 p2 = unpk(acc2[ii][2]);
            float2 p3 = unpk(acc2[ii][3]);
            float4 v0 = make_float4(p0.x+bias[0], p0.y+bias[1], p1.x+bias[2], p1.y+bias[3]);
            float4 v1 = make_float4(p2.x+bias[4], p2.y+bias[5], p3.x+bias[6], p3.y+bias[7]);
            float* orow = &g_gx[(size_t)m * G4 + n0];
            *reinterpret_cast<float4*>(orow + tx*4)      = v0;
            *reinterpret_cast<float4*>(orow + 64 + tx*4) = v1;
        }
    }
}

// ======================================================================
// Kernel 2: persistent LSTM. 64 blocks x 4 batches, 512 threads.
// jg = tid>>7 (4 j-groups of 32 j), k = tid&127 (hidden unit).
// All-FMA2. Gates g,o: register pairs (own j-window). Gates i,f: smem
// pair-transposed (conflict-free LDS.64). h [buf][b][j] broadcast loads.
// 4 batches amortize W-crossbar + barrier + tail fixed costs.
// ======================================================================
#define RSTR2    49
#define OFF_WI   0
#define OFF_WF   (64*128*2)                  // 16384
#define OFF_HS   (OFF_WF + 64*128*2)         // 32768: hs[2][4][128]
#define OFF_RED  (OFF_HS + 1024)             // 33792: red[128][49]
#define SMEM_LS  ((OFF_RED + 128*RSTR2) * 4) // 160256 B

__global__ void __launch_bounds__(512, 1) lstm_kernel(
    const float* __restrict__ W_hh,
    const int*   __restrict__ lengths)
{
    extern __shared__ float sm[];
    float* Wi2 = sm + OFF_WI;
    float* Wf2 = sm + OFF_WF;
    float* hs  = sm + OFF_HS;
    float* red = sm + OFF_RED;

    const int tid = threadIdx.x;
    const int jg  = tid >> 7;
    const int k   = tid & 127;
    const int jb  = jg * 32;
    const int jbp = jg * 16;
    const int b0  = blockIdx.x * 4;

    // stage pair-transposed gates i, f
    for (int idx = tid; idx < 8192; idx += 512) {
        int kk = idx >> 6;
        int jp = idx & 63;
        float2 vi = *reinterpret_cast<const float2*>(&W_hh[(size_t)kk * HH + jp*2]);
        float2 vf = *reinterpret_cast<const float2*>(&W_hh[(size_t)(HH + kk) * HH + jp*2]);
        *reinterpret_cast<float2*>(&Wi2[(jp*128 + kk)*2]) = vi;
        *reinterpret_cast<float2*>(&Wf2[(jp*128 + kk)*2]) = vf;
    }

    // register pairs for gates g, o on own j-window
    ull wg2[16], wo2[16];
    {
        const float* gp = &W_hh[(size_t)(2*HH + k) * HH + jb];
        const float* op = &W_hh[(size_t)(3*HH + k) * HH + jb];
#pragma unroll
        for (int m = 0; m < 8; ++m) {
            ulonglong2 a = *reinterpret_cast<const ulonglong2*>(gp + m*4);
            wg2[m*2] = a.x; wg2[m*2+1] = a.y;
            ulonglong2 b = *reinterpret_cast<const ulonglong2*>(op + m*4);
            wo2[m*2] = b.x; wo2[m*2+1] = b.y;
        }
    }

    int len[4];
#pragma unroll
    for (int bi = 0; bi < 4; ++bi) len[bi] = lengths[b0 + bi];

    float cst[4] = {0.f,0.f,0.f,0.f}, hst[4] = {0.f,0.f,0.f,0.f};
    if (jg == 0) {
#pragma unroll
        for (int bi = 0; bi < 4; ++bi) { hs[bi*128 + k] = 0.f; hs[512 + bi*128 + k] = 0.f; }
    }
    __syncthreads();

    float gxc[4];
    {
        const float* r = g_gx + (size_t)b0 * G4 + jg*HH + k;
#pragma unroll
        for (int bi = 0; bi < 4; ++bi) gxc[bi] = r[(size_t)bi * G4];
    }

    for (int t = 0; t < TT; ++t) {
        float gxn[4] = {0.f,0.f,0.f,0.f};
        if (t + 1 < TT) {
            const float* r = g_gx + ((size_t)(t + 1) * BB + b0) * G4 + jg*HH + k;
#pragma unroll
            for (int bi = 0; bi < 4; ++bi) gxn[bi] = r[(size_t)bi * G4];
        }

        ull acc[4][4];
#pragma unroll
        for (int gi = 0; gi < 4; ++gi)
#pragma unroll
            for (int bi = 0; bi < 4; ++bi)
                acc[gi][bi] = (gi == jg) ? pack2(gxc[bi], 0.f) : 0ULL;

        const float* hb = hs + (t & 1) * 512;

#pragma unroll
        for (int q = 0; q < 8; ++q) {
            ull wia = *reinterpret_cast<const ull*>(&Wi2[((jbp + 2*q    )*128 + k)*2]);
            ull wib = *reinterpret_cast<const ull*>(&Wi2[((jbp + 2*q + 1)*128 + k)*2]);
            ull wfa = *reinterpret_cast<const ull*>(&Wf2[((jbp + 2*q    )*128 + k)*2]);
            ull wfb = *reinterpret_cast<const ull*>(&Wf2[((jbp + 2*q + 1)*128 + k)*2]);
            ull wga = wg2[2*q], wgb = wg2[2*q+1];
            ull woa = wo2[2*q], wob = wo2[2*q+1];
#pragma unroll
            for (int bi = 0; bi < 4; ++bi) {
                ulonglong2 hp = *reinterpret_cast<const ulonglong2*>(&hb[bi*128 + jb + q*4]);
                acc[0][bi] = fma2(wia, hp.x, acc[0][bi]);
                acc[0][bi] = fma2(wib, hp.y, acc[0][bi]);
                acc[1][bi] = fma2(wfa, hp.x, acc[1][bi]);
                acc[1][bi] = fma2(wfb, hp.y, acc[1][bi]);
                acc[2][bi] = fma2(wga, hp.x, acc[2][bi]);
                acc[2][bi] = fma2(wgb, hp.y, acc[2][bi]);
                acc[3][bi] = fma2(woa, hp.x, acc[3][bi]);
                acc[3][bi] = fma2(wob, hp.y, acc[3][bi]);
            }
        }

        float s[4][4];
#pragma unroll
        for (int gi = 0; gi < 4; ++gi)
#pragma unroll
            for (int bi = 0; bi < 4; ++bi)
                s[gi][bi] = sum2(acc[gi][bi]);

        if (jg != 0) {
            float* r = &red[k * RSTR2 + (jg - 1) * 16];
#pragma unroll
            for (int gi = 0; gi < 4; ++gi)
#pragma unroll
                for (int bi = 0; bi < 4; ++bi)
                    r[gi*4 + bi] = s[gi][bi];
        }
        __syncthreads();

        if (jg == 0) {
#pragma unroll
            for (int g2 = 0; g2 < 3; ++g2) {
                const float* r = &red[k * RSTR2 + g2 * 16];
#pragma unroll
                for (int gi = 0; gi < 4; ++gi)
#pragma unroll
                    for (int bi = 0; bi < 4; ++bi)
                        s[gi][bi] += r[gi*4 + bi];
            }
#pragma unroll
            for (int bi = 0; bi < 4; ++bi) {
                float ig = sigf(s[0][bi]), fg = sigf(s[1][bi]);
                float gg = tanhf_fast(s[2][bi]), og = sigf(s[3][bi]);
                float cn = fg * cst[bi] + ig * gg;
                float hn = og * tanhf_fast(cn);
                if (t < len[bi]) { cst[bi] = cn; hst[bi] = hn; }
            }
            float* hnp = hs + ((t + 1) & 1) * 512;
#pragma unroll
            for (int bi = 0; bi < 4; ++bi) hnp[bi*128 + k] = hst[bi];
        }
        __syncthreads();

#pragma unroll
        for (int bi = 0; bi < 4; ++bi) gxc[bi] = gxn[bi];
    }

    if (jg == 0) {
#pragma unroll
        for (int bi = 0; bi < 4; ++bi)
            g_h[(b0 + bi) * HH + k] = hst[bi];
    }
}

// ======================================================================
// Kernel 3: out[b][c] = h[b] . fc_w[c] + fc_b[c]   (256 x 6)
// ======================================================================
__global__ void __launch_bounds__(256) fc_kernel(
    const float* __restrict__ fc_w,
    const float* __restrict__ fc_b,
    float* __restrict__ out)
{
    __shared__ float wsm[CC * HH];
    __shared__ float bsm[CC];
    int tid = threadIdx.x;
    for (int i = tid; i < CC * HH; i += 256) wsm[i] = fc_w[i];
    if (tid < CC) bsm[tid] = fc_b[tid];
    __syncthreads();

    float s[CC];
#pragma unroll
    for (int c = 0; c < CC; ++c) s[c] = bsm[c];
    const float* h = g_h + tid * HH;
#pragma unroll 8
    for (int kk = 0; kk < HH; ++kk) {
        float hk = h[kk];
#pragma unroll
        for (int c = 0; c < CC; ++c) s[c] += hk * wsm[c * HH + kk];
    }
#pragma unroll
    for (int c = 0; c < CC; ++c) out[tid * CC + c] = s[c];
}

// ======================================================================
extern "C" void kernel_launch(void* const* d_in, const int* in_sizes, int n_in,
                              void* d_out, int out_size)
{
    const float* x     = (const float*)d_in[0];
    const float* W_ih  = (const float*)d_in[1];
    const float* W_hh  = (const float*)d_in[2];
    const float* b_ih  = (const float*)d_in[3];
    const float* b_hh  = (const float*)d_in[4];
    const float* fc_w  = (const float*)d_in[5];
    const float* fc_b  = (const float*)d_in[6];
    const int*   lens  = (const int*)d_in[7];
    float* out = (float*)d_out;

    cudaFuncSetAttribute(lstm_kernel, cudaFuncAttributeMaxDynamicSharedMemorySize, SMEM_LS);

    dim3 g1((TT * BB) / 128, G4 / 128);
    gx_kernel<<<g1, 256>>>(x, W_ih, b_ih, b_hh);

    lstm_kernel<<<BB / 4, 512, SMEM_LS>>>(W_hh, lens);

    fc_kernel<<<1, 256>>>(fc_w, fc_b, out);
}

// round 11
// speedup vs baseline: 1.8326x; 1.8326x over previous
#include <cuda_runtime.h>
#include <cuda_bf16.h>
#include <cstdint>

typedef unsigned long long ull;

// Problem constants
#define BB   256
#define TT   512
#define DD   300
#define HH   128
#define G4   512          // 4*H
#define CC   6

// ---------------- scratch (device globals: allocation-free) ----------------
__device__ float g_gx[(size_t)TT * BB * G4];   // [t][b][g]
__device__ float g_h[BB * HH];                 // final hidden

// ---------------- helpers ----------------
__device__ __forceinline__ ull fma2(ull a, ull b, ull c) {
    ull d;
    asm("fma.rn.f32x2 %0, %1, %2, %3;" : "=l"(d) : "l"(a), "l"(b), "l"(c));
    return d;
}
__device__ __forceinline__ ull pack2(float lo, float hi) {
    ull r;
    asm("mov.b64 %0, {%1, %2};" : "=l"(r) : "f"(lo), "f"(hi));
    return r;
}
__device__ __forceinline__ float sum2(ull v) {
    float lo, hi;
    asm("mov.b64 {%0, %1}, %2;" : "=f"(lo), "=f"(hi) : "l"(v));
    return lo + hi;
}
__device__ __forceinline__ float sigf(float x) { return 1.f / (1.f + __expf(-x)); }
__device__ __forceinline__ float tanhf_fast(float x) {
    float e = __expf(-2.f * fabsf(x));
    float r = (1.f - e) / (1.f + e);
    return copysignf(r, x);
}

// m16n8k16 bf16 mma with fp32 accumulate (sm_80 baseline PTX -> HMMA on sm_103)
__device__ __forceinline__ void mma16816(float* c, const uint32_t* a,
                                         uint32_t b0, uint32_t b1) {
    asm volatile(
        "mma.sync.aligned.m16n8k16.row.col.f32.bf16.bf16.f32 "
        "{%0,%1,%2,%3}, {%4,%5,%6,%7}, {%8,%9}, {%0,%1,%2,%3};"
        : "+f"(c[0]), "+f"(c[1]), "+f"(c[2]), "+f"(c[3])
        : "r"(a[0]), "r"(a[1]), "r"(a[2]), "r"(a[3]), "r"(b0), "r"(b1));
}

// ======================================================================
// Kernel 1: gx = x @ W_ih^T + b_ih + b_hh  via bf16 hi/lo split + mma.sync
// Block: 128 (M, batch rows at fixed t) x 128 (N, gates). 256 thr = 8 warps
// in 4x2; each warp 32x64 via 2x8 m16n8k16 tiles. K: 5 slabs of 64
// (K=300 zero-padded to 320). Smem row stride 72 bf16 -> all fragment
// LDS conflict-free (bank = 4*g + t4 + const).
// D = Ahi*Bhi + Ahi*Blo + Alo*Bhi  (fp32 accum; lo*lo dropped ~2^-18)
// ======================================================================
#define STR    72
#define GOFF_AHI  0
#define GOFF_ALO  18432
#define GOFF_BHI  36864
#define GOFF_BLO  55296
#define GOFF_BIAS 73728
#define SMEM_GX   (GOFF_BIAS + 512)   // 74240 B

__global__ void __launch_bounds__(256, 2) gx_kernel(
    const float* __restrict__ x,
    const float* __restrict__ W_ih,
    const float* __restrict__ b_ih,
    const float* __restrict__ b_hh)
{
    extern __shared__ char sm[];
    __nv_bfloat16* Ahi = reinterpret_cast<__nv_bfloat16*>(sm + GOFF_AHI);
    __nv_bfloat16* Alo = reinterpret_cast<__nv_bfloat16*>(sm + GOFF_ALO);
    __nv_bfloat16* Bhi = reinterpret_cast<__nv_bfloat16*>(sm + GOFF_BHI);
    __nv_bfloat16* Blo = reinterpret_cast<__nv_bfloat16*>(sm + GOFF_BLO);
    float* bsm = reinterpret_cast<float*>(sm + GOFF_BIAS);

    const int tid  = threadIdx.x;
    const int wid  = tid >> 5;
    const int lane = tid & 31;
    const int g    = lane >> 2;        // groupID 0..7
    const int t4   = lane & 3;         // thread-in-group

    const int wr = wid & 3;            // warp M quarter (32 rows)
    const int wc = wid >> 2;           // warp N half (64 cols)

    const int m0  = blockIdx.x * 128;
    const int n0  = blockIdx.y * 128;
    const int t   = m0 >> 8;           // 128 rows stay within one t
    const int b0p = m0 & 255;

    if (tid < 128) bsm[tid] = b_ih[n0 + tid] + b_hh[n0 + tid];

    float acc[2][8][4];
#pragma unroll
    for (int mt = 0; mt < 2; ++mt)
#pragma unroll
        for (int nt = 0; nt < 8; ++nt)
#pragma unroll
            for (int r = 0; r < 4; ++r) acc[mt][nt][r] = 0.f;

    for (int s = 0; s < 5; ++s) {
        if (s) __syncthreads();        // protect smem from prior slab's readers

        // load + hi/lo convert + store (float2 gmem, packed bf16x2 STS.32)
        for (int i = tid; i < 4096; i += 256) {
            int row = i >> 5;
            int kp  = i & 31;
            int kg  = s * 64 + kp * 2;
            float2 va = make_float2(0.f, 0.f), vb = make_float2(0.f, 0.f);
            if (kg < DD) {
                va = *reinterpret_cast<const float2*>(
                        &x[((size_t)(b0p + row) * TT + t) * DD + kg]);
                vb = *reinterpret_cast<const float2*>(
                        &W_ih[(size_t)(n0 + row) * DD + kg]);
            }
            __nv_bfloat16 ah0 = __float2bfloat16(va.x);
            __nv_bfloat16 ah1 = __float2bfloat16(va.y);
            __nv_bfloat16 al0 = __float2bfloat16(va.x - __bfloat162float(ah0));
            __nv_bfloat16 al1 = __float2bfloat16(va.y - __bfloat162float(ah1));
            __nv_bfloat16 bh0 = __float2bfloat16(vb.x);
            __nv_bfloat16 bh1 = __float2bfloat16(vb.y);
            __nv_bfloat16 bl0 = __float2bfloat16(vb.x - __bfloat162float(bh0));
            __nv_bfloat16 bl1 = __float2bfloat16(vb.y - __bfloat162float(bh1));
            uint32_t pa = (uint32_t)__bfloat16_as_ushort(ah0) | ((uint32_t)__bfloat16_as_ushort(ah1) << 16);
            uint32_t pl = (uint32_t)__bfloat16_as_ushort(al0) | ((uint32_t)__bfloat16_as_ushort(al1) << 16);
            uint32_t pb = (uint32_t)__bfloat16_as_ushort(bh0) | ((uint32_t)__bfloat16_as_ushort(bh1) << 16);
            uint32_t pq = (uint32_t)__bfloat16_as_ushort(bl0) | ((uint32_t)__bfloat16_as_ushort(bl1) << 16);
            int so = row * STR + kp * 2;
            *reinterpret_cast<uint32_t*>(&Ahi[so]) = pa;
            *reinterpret_cast<uint32_t*>(&Alo[so]) = pl;
            *reinterpret_cast<uint32_t*>(&Bhi[so]) = pb;
            *reinterpret_cast<uint32_t*>(&Blo[so]) = pq;
        }
        __syncthreads();

        // compute: 4 k16 steps over the 64-wide slab
#pragma unroll
        for (int ks = 0; ks < 4; ++ks) {
            const int kb = ks * 16;
            uint32_t ahf[2][4], alf[2][4];
#pragma unroll
            for (int mt = 0; mt < 2; ++mt) {
                int r0 = (wr * 32 + mt * 16 + g) * STR + kb + t4 * 2;
                int r1 = r0 + 8 * STR;
                // a0:(row g, k), a1:(row g+8, k), a2:(row g, k+8), a3:(row g+8, k+8)
                ahf[mt][0] = *reinterpret_cast<const uint32_t*>(&Ahi[r0]);
                ahf[mt][1] = *reinterpret_cast<const uint32_t*>(&Ahi[r1]);
                ahf[mt][2] = *reinterpret_cast<const uint32_t*>(&Ahi[r0 + 8]);
                ahf[mt][3] = *reinterpret_cast<const uint32_t*>(&Ahi[r1 + 8]);
                alf[mt][0] = *reinterpret_cast<const uint32_t*>(&Alo[r0]);
                alf[mt][1] = *reinterpret_cast<const uint32_t*>(&Alo[r1]);
                alf[mt][2] = *reinterpret_cast<const uint32_t*>(&Alo[r0 + 8]);
                alf[mt][3] = *reinterpret_cast<const uint32_t*>(&Alo[r1 + 8]);
            }
#pragma unroll
            for (int nt = 0; nt < 8; ++nt) {
                int br = (wc * 64 + nt * 8 + g) * STR + kb + t4 * 2;
                uint32_t bh0 = *reinterpret_cast<const uint32_t*>(&Bhi[br]);
                uint32_t bh1 = *reinterpret_cast<const uint32_t*>(&Bhi[br + 8]);
                uint32_t bl0 = *reinterpret_cast<const uint32_t*>(&Blo[br]);
                uint32_t bl1 = *reinterpret_cast<const uint32_t*>(&Blo[br + 8]);
#pragma unroll
                for (int mt = 0; mt < 2; ++mt) {
                    mma16816(acc[mt][nt], ahf[mt], bh0, bh1);
                    mma16816(acc[mt][nt], ahf[mt], bl0, bl1);
                    mma16816(acc[mt][nt], alf[mt], bh0, bh1);
                }
            }
        }
    }

    // epilogue: c0:(row g, col 2t4), c1:(+1), c2:(row g+8, col 2t4), c3:(+1)
#pragma unroll
    for (int mt = 0; mt < 2; ++mt) {
#pragma unroll
        for (int nt = 0; nt < 8; ++nt) {
            int mrow = m0 + wr * 32 + mt * 16 + g;
            int nc   = wc * 64 + nt * 8 + t4 * 2;
            float b0v = bsm[nc], b1v = bsm[nc + 1];
            float2 v0 = make_float2(acc[mt][nt][0] + b0v, acc[mt][nt][1] + b1v);
            float2 v1 = make_float2(acc[mt][nt][2] + b0v, acc[mt][nt][3] + b1v);
            *reinterpret_cast<float2*>(&g_gx[(size_t)mrow * G4 + n0 + nc]) = v0;
            *reinterpret_cast<float2*>(&g_gx[(size_t)(mrow + 8) * G4 + n0 + nc]) = v1;
        }
    }
}

// ======================================================================
// Kernel 2: persistent LSTM (round-4 proven version, 794us).
// 128 blocks x 2 batches, 512 threads. jg = tid>>7 (4 j-groups of 32 j),
// k = tid&127. FMA2 over natural j-pairs. Gates g,o: register pairs.
// Gates i,f: smem pair-transposed (conflict-free LDS.64). 2 barriers/step.
// ======================================================================
#define RSTR    25
#define OFF_WI  0
#define OFF_WF  (64*128*2)
#define OFF_HS  (OFF_WF + 64*128*2)
#define OFF_RED (OFF_HS + 512)
#define SMEM_LS ((OFF_RED + 128*RSTR) * 4)

__global__ void __launch_bounds__(512, 1) lstm_kernel(
    const float* __restrict__ W_hh,
    const int*   __restrict__ lengths)
{
    extern __shared__ float smf[];
    float* Wi2 = smf + OFF_WI;
    float* Wf2 = smf + OFF_WF;
    float* hs  = smf + OFF_HS;
    float* red = smf + OFF_RED;

    const int tid = threadIdx.x;
    const int jg  = tid >> 7;
    const int k   = tid & 127;
    const int jb  = jg * 32;
    const int jbp = jg * 16;
    const int b0  = blockIdx.x * 2;

    for (int idx = tid; idx < 8192; idx += 512) {
        int kk = idx >> 6;
        int jp = idx & 63;
        float2 vi = *reinterpret_cast<const float2*>(&W_hh[(size_t)kk * HH + jp*2]);
        float2 vf = *reinterpret_cast<const float2*>(&W_hh[(size_t)(HH + kk) * HH + jp*2]);
        *reinterpret_cast<float2*>(&Wi2[(jp*128 + kk)*2]) = vi;
        *reinterpret_cast<float2*>(&Wf2[(jp*128 + kk)*2]) = vf;
    }

    ull wg2[16], wo2[16];
    {
        const float* gp = &W_hh[(size_t)(2*HH + k) * HH + jb];
        const float* op = &W_hh[(size_t)(3*HH + k) * HH + jb];
#pragma unroll
        for (int m = 0; m < 8; ++m) {
            ulonglong2 a = *reinterpret_cast<const ulonglong2*>(gp + m*4);
            wg2[m*2] = a.x; wg2[m*2+1] = a.y;
            ulonglong2 b = *reinterpret_cast<const ulonglong2*>(op + m*4);
            wo2[m*2] = b.x; wo2[m*2+1] = b.y;
        }
    }

    const int len0 = lengths[b0], len1 = lengths[b0 + 1];
    float c0 = 0.f, c1 = 0.f, h0 = 0.f, h1 = 0.f;
    if (jg == 0) { hs[k] = 0.f; hs[128+k] = 0.f; hs[256+k] = 0.f; hs[384+k] = 0.f; }
    __syncthreads();

    float gxc0, gxc1;
    {
        const float* r = g_gx + (size_t)b0 * G4;
        gxc0 = r[jg*HH + k];
        gxc1 = r[G4 + jg*HH + k];
    }

    for (int t = 0; t < TT; ++t) {
        float gxn0 = 0.f, gxn1 = 0.f;
        if (t + 1 < TT) {
            const float* r = g_gx + (size_t)((t + 1) * BB + b0) * G4;
            gxn0 = r[jg*HH + k];
            gxn1 = r[G4 + jg*HH + k];
        }

        ull acc[4][2];
#pragma unroll
        for (int gi = 0; gi < 4; ++gi) {
            acc[gi][0] = pack2((gi == jg) ? gxc0 : 0.f, 0.f);
            acc[gi][1] = pack2((gi == jg) ? gxc1 : 0.f, 0.f);
        }

        const float* hb = hs + (t & 1) * 256;
        const ulonglong2* h0p = reinterpret_cast<const ulonglong2*>(hb + jb);
        const ulonglong2* h1p = reinterpret_cast<const ulonglong2*>(hb + 128 + jb);

#pragma unroll
        for (int q = 0; q < 8; ++q) {
            ulonglong2 hp0 = h0p[q];
            ulonglong2 hp1 = h1p[q];
            ull wia = *reinterpret_cast<const ull*>(&Wi2[((jbp + 2*q    )*128 + k)*2]);
            ull wib = *reinterpret_cast<const ull*>(&Wi2[((jbp + 2*q + 1)*128 + k)*2]);
            ull wfa = *reinterpret_cast<const ull*>(&Wf2[((jbp + 2*q    )*128 + k)*2]);
            ull wfb = *reinterpret_cast<const ull*>(&Wf2[((jbp + 2*q + 1)*128 + k)*2]);

            acc[0][0] = fma2(wia, hp0.x, acc[0][0]);
            acc[0][0] = fma2(wib, hp0.y, acc[0][0]);
            acc[0][1] = fma2(wia, hp1.x, acc[0][1]);
            acc[0][1] = fma2(wib, hp1.y, acc[0][1]);

            acc[1][0] = fma2(wfa, hp0.x, acc[1][0]);
            acc[1][0] = fma2(wfb, hp0.y, acc[1][0]);
            acc[1][1] = fma2(wfa, hp1.x, acc[1][1]);
            acc[1][1] = fma2(wfb, hp1.y, acc[1][1]);

            acc[2][0] = fma2(wg2[2*q],   hp0.x, acc[2][0]);
            acc[2][0] = fma2(wg2[2*q+1], hp0.y, acc[2][0]);
            acc[2][1] = fma2(wg2[2*q],   hp1.x, acc[2][1]);
            acc[2][1] = fma2(wg2[2*q+1], hp1.y, acc[2][1]);

            acc[3][0] = fma2(wo2[2*q],   hp0.x, acc[3][0]);
            acc[3][0] = fma2(wo2[2*q+1], hp0.y, acc[3][0]);
            acc[3][1] = fma2(wo2[2*q],   hp1.x, acc[3][1]);
            acc[3][1] = fma2(wo2[2*q+1], hp1.y, acc[3][1]);
        }

        float s00 = sum2(acc[0][0]), s01 = sum2(acc[0][1]);
        float s10 = sum2(acc[1][0]), s11 = sum2(acc[1][1]);
        float s20 = sum2(acc[2][0]), s21 = sum2(acc[2][1]);
        float s30 = sum2(acc[3][0]), s31 = sum2(acc[3][1]);

        if (jg != 0) {
            float* r = &red[k * RSTR + (jg - 1) * 8];
            r[0] = s00; r[1] = s01; r[2] = s10; r[3] = s11;
            r[4] = s20; r[5] = s21; r[6] = s30; r[7] = s31;
        }
        __syncthreads();

        if (jg == 0) {
#pragma unroll
            for (int g2 = 0; g2 < 3; ++g2) {
                const float* r = &red[k * RSTR + g2 * 8];
                s00 += r[0]; s01 += r[1]; s10 += r[2]; s11 += r[3];
                s20 += r[4]; s21 += r[5]; s30 += r[6]; s31 += r[7];
            }
            {
                float ig = sigf(s00), fg = sigf(s10);
                float gg = tanhf_fast(s20), og = sigf(s30);
                float cn = fg * c0 + ig * gg;
                float hn = og * tanhf_fast(cn);
                if (t < len0) { c0 = cn; h0 = hn; }
            }
            {
                float ig = sigf(s01), fg = sigf(s11);
                float gg = tanhf_fast(s21), og = sigf(s31);
                float cn = fg * c1 + ig * gg;
                float hn = og * tanhf_fast(cn);
                if (t < len1) { c1 = cn; h1 = hn; }
            }
            float* hn = hs + ((t + 1) & 1) * 256;
            hn[k] = h0; hn[128 + k] = h1;
        }
        __syncthreads();

        gxc0 = gxn0; gxc1 = gxn1;
    }

    if (jg == 0) {
        g_h[(b0 + 0) * HH + k] = h0;
        g_h[(b0 + 1) * HH + k] = h1;
    }
}

// ======================================================================
// Kernel 3: out[b][c] = h[b] . fc_w[c] + fc_b[c]   (256 x 6)
// ======================================================================
__global__ void __launch_bounds__(256) fc_kernel(
    const float* __restrict__ fc_w,
    const float* __restrict__ fc_b,
    float* __restrict__ out)
{
    __shared__ float wsm[CC * HH];
    __shared__ float bsm2[CC];
    int tid = threadIdx.x;
    for (int i = tid; i < CC * HH; i += 256) wsm[i] = fc_w[i];
    if (tid < CC) bsm2[tid] = fc_b[tid];
    __syncthreads();

    float s[CC];
#pragma unroll
    for (int c = 0; c < CC; ++c) s[c] = bsm2[c];
    const float* h = g_h + tid * HH;
#pragma unroll 8
    for (int kk = 0; kk < HH; ++kk) {
        float hk = h[kk];
#pragma unroll
        for (int c = 0; c < CC; ++c) s[c] += hk * wsm[c * HH + kk];
    }
#pragma unroll
    for (int c = 0; c < CC; ++c) out[tid * CC + c] = s[c];
}

// ======================================================================
extern "C" void kernel_launch(void* const* d_in, const int* in_sizes, int n_in,
                              void* d_out, int out_size)
{
    const float* x     = (const float*)d_in[0];
    const float* W_ih  = (const float*)d_in[1];
    const float* W_hh  = (const float*)d_in[2];
    const float* b_ih  = (const float*)d_in[3];
    const float* b_hh  = (const float*)d_in[4];
    const float* fc_w  = (const float*)d_in[5];
    const float* fc_b  = (const float*)d_in[6];
    const int*   lens  = (const int*)d_in[7];
    float* out = (float*)d_out;

    cudaFuncSetAttribute(gx_kernel, cudaFuncAttributeMaxDynamicSharedMemorySize, SMEM_GX);
    cudaFuncSetAttribute(lstm_kernel, cudaFuncAttributeMaxDynamicSharedMemorySize, SMEM_LS);

    dim3 g1((TT * BB) / 128, G4 / 128);   // 1024 x 4
    gx_kernel<<<g1, 256, SMEM_GX>>>(x, W_ih, b_ih, b_hh);

    lstm_kernel<<<BB / 2, 512, SMEM_LS>>>(W_hh, lens);

    fc_kernel<<<1, 256>>>(fc_w, fc_b, out);
}

// round 15
// speedup vs baseline: 1.9968x; 1.0896x over previous
#include <cuda_runtime.h>
#include <cuda_bf16.h>
#include <cstdint>

typedef unsigned long long ull;

// Problem constants
#define BB   256
#define TT   512
#define DD   300
#define HH   128
#define G4   512          // 4*H
#define CC   6
#define KP   320          // K padded

// ---------------- scratch (device globals: allocation-free) ----------------
__device__ float g_gx[(size_t)TT * BB * G4];                 // [t][b][g]
__device__ float g_h[BB * HH];                               // final hidden
// NOTE: g_xhi/g_xlo are stored in M-ORDER: row m = t*BB + b  (matches g_gx)
__device__ __nv_bfloat16 g_xhi[(size_t)BB * TT * KP];
__device__ __nv_bfloat16 g_xlo[(size_t)BB * TT * KP];
__device__ __nv_bfloat16 g_whi[(size_t)G4 * KP];             // W_ih hi
__device__ __nv_bfloat16 g_wlo[(size_t)G4 * KP];             // W_ih lo

// ---------------- helpers ----------------
__device__ __forceinline__ ull fma2(ull a, ull b, ull c) {
    ull d;
    asm("fma.rn.f32x2 %0, %1, %2, %3;" : "=l"(d) : "l"(a), "l"(b), "l"(c));
    return d;
}
__device__ __forceinline__ ull pack2(float lo, float hi) {
    ull r;
    asm("mov.b64 %0, {%1, %2};" : "=l"(r) : "f"(lo), "f"(hi));
    return r;
}
__device__ __forceinline__ float sum2(ull v) {
    float lo, hi;
    asm("mov.b64 {%0, %1}, %2;" : "=f"(lo), "=f"(hi) : "l"(v));
    return lo + hi;
}
__device__ __forceinline__ float sigf(float x) { return 1.f / (1.f + __expf(-x)); }
__device__ __forceinline__ float tanhf_fast(float x) {
    float e = __expf(-2.f * fabsf(x));
    float r = (1.f - e) / (1.f + e);
    return copysignf(r, x);
}
__device__ __forceinline__ void cp16(void* smem_dst, const void* gsrc) {
    uint32_t sa = (uint32_t)__cvta_generic_to_shared(smem_dst);
    asm volatile("cp.async.cg.shared.global [%0], [%1], 16;\n" :: "r"(sa), "l"(gsrc));
}
__device__ __forceinline__ void cp_commit() { asm volatile("cp.async.commit_group;\n" ::: "memory"); }

// m16n8k16 bf16 mma, fp32 accum (sm_80 baseline PTX -> HMMA)
__device__ __forceinline__ void mma16816(float* c, const uint32_t* a,
                                         uint32_t b0, uint32_t b1) {
    asm volatile(
        "mma.sync.aligned.m16n8k16.row.col.f32.bf16.bf16.f32 "
        "{%0,%1,%2,%3}, {%4,%5,%6,%7}, {%8,%9}, {%0,%1,%2,%3};"
        : "+f"(c[0]), "+f"(c[1]), "+f"(c[2]), "+f"(c[3])
        : "r"(a[0]), "r"(a[1]), "r"(a[2]), "r"(a[3]), "r"(b0), "r"(b1));
}

// ======================================================================
// Kernel 0: fp32 -> bf16 hi/lo precompute, zero-pad K to 320.
// x rows are TRANSPOSED to m-order: m = t*BB + b  (x layout is [b][t][d]).
// ======================================================================
#define NXP ((size_t)BB * TT * (KP/2))      // x pairs
#define NWP ((size_t)G4 * (KP/2))           // W pairs

__global__ void __launch_bounds__(256) precvt_kernel(
    const float* __restrict__ x,
    const float* __restrict__ W_ih)
{
    size_t idx = (size_t)blockIdx.x * 256 + threadIdx.x;
    size_t total = NXP + NWP;
    if (idx >= total) return;

    const float* src;
    __nv_bfloat16 *dhi, *dlo;
    size_t kp;
    if (idx < NXP) {
        size_t row_lin = idx / (KP/2);      // x-linear row = b*TT + t
        kp = idx % (KP/2);
        size_t b = row_lin / TT;
        size_t t = row_lin % TT;
        size_t m = t * BB + b;              // m-order row
        src = x + row_lin * DD;
        dhi = g_xhi + m * KP; dlo = g_xlo + m * KP;
    } else {
        size_t j = idx - NXP;
        size_t row = j / (KP/2);
        kp = j % (KP/2);
        src = W_ih + row * DD;
        dhi = g_whi + row * KP; dlo = g_wlo + row * KP;
    }
    int kg = (int)kp * 2;
    float2 v = (kg < DD) ? *reinterpret_cast<const float2*>(src + kg) : make_float2(0.f, 0.f);
    __nv_bfloat16 h0 = __float2bfloat16(v.x);
    __nv_bfloat16 h1 = __float2bfloat16(v.y);
    __nv_bfloat16 l0 = __float2bfloat16(v.x - __bfloat162float(h0));
    __nv_bfloat16 l1 = __float2bfloat16(v.y - __bfloat162float(h1));
    uint32_t ph = (uint32_t)__bfloat16_as_ushort(h0) | ((uint32_t)__bfloat16_as_ushort(h1) << 16);
    uint32_t pl = (uint32_t)__bfloat16_as_ushort(l0) | ((uint32_t)__bfloat16_as_ushort(l1) << 16);
    *reinterpret_cast<uint32_t*>(dhi + kg) = ph;
    *reinterpret_cast<uint32_t*>(dlo + kg) = pl;
}

// ======================================================================
// Kernel 1: gx = x @ W_ih^T + bias  -- pure-bf16 HMMA, cp.async pipeline
// Block 128x128, 256 thr = 8 warps (4x2), warp 32x64 (2x8 m16n8k16).
// K: 10 slabs of 32, double-buffered. Smem rows stride 40 bf16 (80 B):
// word index = 20*row + t4 (+kb/2) -> all 32 lanes distinct banks.
// D = Ahi*Bhi + Ahi*Blo + Alo*Bhi (fp32 accum).
// A rows (g_xhi/g_xlo) are m-ordered, so (m0 + r) indexes directly.
// ======================================================================
#define SSTR   40                            // bf16 words per row
#define ARR_B  (128 * SSTR * 2)              // 10240 B per array
#define BUF_B  (4 * ARR_B)                   // 40960 B per buffer
#define SMEM_GX (2 * BUF_B + 512)            // 82432 B

__global__ void __launch_bounds__(256, 2) gx_kernel(
    const float* __restrict__ b_ih,
    const float* __restrict__ b_hh)
{
    extern __shared__ char sm[];
    float* bsm = reinterpret_cast<float*>(sm + 2 * BUF_B);

    const int tid  = threadIdx.x;
    const int wid  = tid >> 5;
    const int lane = tid & 31;
    const int g    = lane >> 2;
    const int t4   = lane & 3;

    const int wr = wid & 3;            // warp M quarter
    const int wc = wid >> 2;           // warp N half

    const int m0  = blockIdx.x * 128;
    const int n0  = blockIdx.y * 128;

    if (tid < 128) bsm[tid] = b_ih[n0 + tid] + b_hh[n0 + tid];

    float acc[2][8][4];
#pragma unroll
    for (int mt = 0; mt < 2; ++mt)
#pragma unroll
        for (int nt = 0; nt < 8; ++nt)
#pragma unroll
            for (int r = 0; r < 4; ++r) acc[mt][nt][r] = 0.f;

    // issue slab s into buffer buf
    auto issue_slab = [&](int s, int buf) {
        char* base = sm + buf * BUF_B;
#pragma unroll
        for (int it = 0; it < 8; ++it) {
            int i   = it * 256 + tid;      // 0..2047
            int arr = i >> 9;              // 0..3 : Ahi, Alo, Bhi, Blo
            int r   = (i >> 2) & 127;
            int c   = i & 3;
            const __nv_bfloat16* gsrc;
            if (arr == 0)      gsrc = g_xhi + (size_t)(m0 + r) * KP;
            else if (arr == 1) gsrc = g_xlo + (size_t)(m0 + r) * KP;
            else if (arr == 2) gsrc = g_whi + (size_t)(n0 + r) * KP;
            else               gsrc = g_wlo + (size_t)(n0 + r) * KP;
            cp16(base + arr * ARR_B + (r * SSTR + c * 8) * 2,
                 reinterpret_cast<const char*>(gsrc) + s * 64 + c * 16);
        }
        cp_commit();
    };

    issue_slab(0, 0);

    for (int s = 0; s < 10; ++s) {
        if (s + 1 < 10) issue_slab(s + 1, (s + 1) & 1);
        if (s + 1 < 10) { asm volatile("cp.async.wait_group 1;\n" ::: "memory"); }
        else            { asm volatile("cp.async.wait_group 0;\n" ::: "memory"); }
        __syncthreads();

        char* base = sm + (s & 1) * BUF_B;
        __nv_bfloat16* Ahi = reinterpret_cast<__nv_bfloat16*>(base);
        __nv_bfloat16* Alo = reinterpret_cast<__nv_bfloat16*>(base + ARR_B);
        __nv_bfloat16* Bhi = reinterpret_cast<__nv_bfloat16*>(base + 2 * ARR_B);
        __nv_bfloat16* Blo = reinterpret_cast<__nv_bfloat16*>(base + 3 * ARR_B);

#pragma unroll
        for (int ks = 0; ks < 2; ++ks) {
            const int kb = ks * 16;
            uint32_t ahf[2][4], alf[2][4];
#pragma unroll
            for (int mt = 0; mt < 2; ++mt) {
                int r0 = (wr * 32 + mt * 16 + g) * SSTR + kb + t4 * 2;
                int r1 = r0 + 8 * SSTR;
                ahf[mt][0] = *reinterpret_cast<const uint32_t*>(&Ahi[r0]);
                ahf[mt][1] = *reinterpret_cast<const uint32_t*>(&Ahi[r1]);
                ahf[mt][2] = *reinterpret_cast<const uint32_t*>(&Ahi[r0 + 8]);
                ahf[mt][3] = *reinterpret_cast<const uint32_t*>(&Ahi[r1 + 8]);
                alf[mt][0] = *reinterpret_cast<const uint32_t*>(&Alo[r0]);
                alf[mt][1] = *reinterpret_cast<const uint32_t*>(&Alo[r1]);
                alf[mt][2] = *reinterpret_cast<const uint32_t*>(&Alo[r0 + 8]);
                alf[mt][3] = *reinterpret_cast<const uint32_t*>(&Alo[r1 + 8]);
            }
#pragma unroll
            for (int nt = 0; nt < 8; ++nt) {
                int br = (wc * 64 + nt * 8 + g) * SSTR + kb + t4 * 2;
                uint32_t bh0 = *reinterpret_cast<const uint32_t*>(&Bhi[br]);
                uint32_t bh1 = *reinterpret_cast<const uint32_t*>(&Bhi[br + 8]);
                uint32_t bl0 = *reinterpret_cast<const uint32_t*>(&Blo[br]);
                uint32_t bl1 = *reinterpret_cast<const uint32_t*>(&Blo[br + 8]);
#pragma unroll
                for (int mt = 0; mt < 2; ++mt) {
                    mma16816(acc[mt][nt], ahf[mt], bh0, bh1);
                    mma16816(acc[mt][nt], ahf[mt], bl0, bl1);
                    mma16816(acc[mt][nt], alf[mt], bh0, bh1);
                }
            }
        }
        __syncthreads();
    }

    // epilogue
#pragma unroll
    for (int mt = 0; mt < 2; ++mt) {
#pragma unroll
        for (int nt = 0; nt < 8; ++nt) {
            int mrow = m0 + wr * 32 + mt * 16 + g;
            int nc   = wc * 64 + nt * 8 + t4 * 2;
            float b0v = bsm[nc], b1v = bsm[nc + 1];
            float2 v0 = make_float2(acc[mt][nt][0] + b0v, acc[mt][nt][1] + b1v);
            float2 v1 = make_float2(acc[mt][nt][2] + b0v, acc[mt][nt][3] + b1v);
            *reinterpret_cast<float2*>(&g_gx[(size_t)mrow * G4 + n0 + nc]) = v0;
            *reinterpret_cast<float2*>(&g_gx[(size_t)(mrow + 8) * G4 + n0 + nc]) = v1;
        }
    }
}

// ======================================================================
// Kernel 2: persistent LSTM (round-4 proven version).
// ======================================================================
#define RSTR    25
#define OFF_WI  0
#define OFF_WF  (64*128*2)
#define OFF_HS  (OFF_WF + 64*128*2)
#define OFF_RED (OFF_HS + 512)
#define SMEM_LS ((OFF_RED + 128*RSTR) * 4)

__global__ void __launch_bounds__(512, 1) lstm_kernel(
    const float* __restrict__ W_hh,
    const int*   __restrict__ lengths)
{
    extern __shared__ float smf[];
    float* Wi2 = smf + OFF_WI;
    float* Wf2 = smf + OFF_WF;
    float* hs  = smf + OFF_HS;
    float* red = smf + OFF_RED;

    const int tid = threadIdx.x;
    const int jg  = tid >> 7;
    const int k   = tid & 127;
    const int jb  = jg * 32;
    const int jbp = jg * 16;
    const int b0  = blockIdx.x * 2;

    for (int idx = tid; idx < 8192; idx += 512) {
        int kk = idx >> 6;
        int jp = idx & 63;
        float2 vi = *reinterpret_cast<const float2*>(&W_hh[(size_t)kk * HH + jp*2]);
        float2 vf = *reinterpret_cast<const float2*>(&W_hh[(size_t)(HH + kk) * HH + jp*2]);
        *reinterpret_cast<float2*>(&Wi2[(jp*128 + kk)*2]) = vi;
        *reinterpret_cast<float2*>(&Wf2[(jp*128 + kk)*2]) = vf;
    }

    ull wg2[16], wo2[16];
    {
        const float* gp = &W_hh[(size_t)(2*HH + k) * HH + jb];
        const float* op = &W_hh[(size_t)(3*HH + k) * HH + jb];
#pragma unroll
        for (int m = 0; m < 8; ++m) {
            ulonglong2 a = *reinterpret_cast<const ulonglong2*>(gp + m*4);
            wg2[m*2] = a.x; wg2[m*2+1] = a.y;
            ulonglong2 b = *reinterpret_cast<const ulonglong2*>(op + m*4);
            wo2[m*2] = b.x; wo2[m*2+1] = b.y;
        }
    }

    const int len0 = lengths[b0], len1 = lengths[b0 + 1];
    float c0 = 0.f, c1 = 0.f, h0 = 0.f, h1 = 0.f;
    if (jg == 0) { hs[k] = 0.f; hs[128+k] = 0.f; hs[256+k] = 0.f; hs[384+k] = 0.f; }
    __syncthreads();

    float gxc0, gxc1;
    {
        const float* r = g_gx + (size_t)b0 * G4;
        gxc0 = r[jg*HH + k];
        gxc1 = r[G4 + jg*HH + k];
    }

    for (int t = 0; t < TT; ++t) {
        float gxn0 = 0.f, gxn1 = 0.f;
        if (t + 1 < TT) {
            const float* r = g_gx + (size_t)((t + 1) * BB + b0) * G4;
            gxn0 = r[jg*HH + k];
            gxn1 = r[G4 + jg*HH + k];
        }

        ull acc[4][2];
#pragma unroll
        for (int gi = 0; gi < 4; ++gi) {
            acc[gi][0] = pack2((gi == jg) ? gxc0 : 0.f, 0.f);
            acc[gi][1] = pack2((gi == jg) ? gxc1 : 0.f, 0.f);
        }

        const float* hb = hs + (t & 1) * 256;
        const ulonglong2* h0p = reinterpret_cast<const ulonglong2*>(hb + jb);
        const ulonglong2* h1p = reinterpret_cast<const ulonglong2*>(hb + 128 + jb);

#pragma unroll
        for (int q = 0; q < 8; ++q) {
            ulonglong2 hp0 = h0p[q];
            ulonglong2 hp1 = h1p[q];
            ull wia = *reinterpret_cast<const ull*>(&Wi2[((jbp + 2*q    )*128 + k)*2]);
            ull wib = *reinterpret_cast<const ull*>(&Wi2[((jbp + 2*q + 1)*128 + k)*2]);
            ull wfa = *reinterpret_cast<const ull*>(&Wf2[((jbp + 2*q    )*128 + k)*2]);
            ull wfb = *reinterpret_cast<const ull*>(&Wf2[((jbp + 2*q + 1)*128 + k)*2]);

            acc[0][0] = fma2(wia, hp0.x, acc[0][0]);
            acc[0][0] = fma2(wib, hp0.y, acc[0][0]);
            acc[0][1] = fma2(wia, hp1.x, acc[0][1]);
            acc[0][1] = fma2(wib, hp1.y, acc[0][1]);

            acc[1][0] = fma2(wfa, hp0.x, acc[1][0]);
            acc[1][0] = fma2(wfb, hp0.y, acc[1][0]);
            acc[1][1] = fma2(wfa, hp1.x, acc[1][1]);
            acc[1][1] = fma2(wfb, hp1.y, acc[1][1]);

            acc[2][0] = fma2(wg2[2*q],   hp0.x, acc[2][0]);
            acc[2][0] = fma2(wg2[2*q+1], hp0.y, acc[2][0]);
            acc[2][1] = fma2(wg2[2*q],   hp1.x, acc[2][1]);
            acc[2][1] = fma2(wg2[2*q+1], hp1.y, acc[2][1]);

            acc[3][0] = fma2(wo2[2*q],   hp0.x, acc[3][0]);
            acc[3][0] = fma2(wo2[2*q+1], hp0.y, acc[3][0]);
            acc[3][1] = fma2(wo2[2*q],   hp1.x, acc[3][1]);
            acc[3][1] = fma2(wo2[2*q+1], hp1.y, acc[3][1]);
        }

        float s00 = sum2(acc[0][0]), s01 = sum2(acc[0][1]);
        float s10 = sum2(acc[1][0]), s11 = sum2(acc[1][1]);
        float s20 = sum2(acc[2][0]), s21 = sum2(acc[2][1]);
        float s30 = sum2(acc[3][0]), s31 = sum2(acc[3][1]);

        if (jg != 0) {
            float* r = &red[k * RSTR + (jg - 1) * 8];
            r[0] = s00; r[1] = s01; r[2] = s10; r[3] = s11;
            r[4] = s20; r[5] = s21; r[6] = s30; r[7] = s31;
        }
        __syncthreads();

        if (jg == 0) {
#pragma unroll
            for (int g2 = 0; g2 < 3; ++g2) {
                const float* r = &red[k * RSTR + g2 * 8];
                s00 += r[0]; s01 += r[1]; s10 += r[2]; s11 += r[3];
                s20 += r[4]; s21 += r[5]; s30 += r[6]; s31 += r[7];
            }
            {
                float ig = sigf(s00), fg = sigf(s10);
                float gg = tanhf_fast(s20), og = sigf(s30);
                float cn = fg * c0 + ig * gg;
                float hn = og * tanhf_fast(cn);
                if (t < len0) { c0 = cn; h0 = hn; }
            }
            {
                float ig = sigf(s01), fg = sigf(s11);
                float gg = tanhf_fast(s21), og = sigf(s31);
                float cn = fg * c1 + ig * gg;
                float hn = og * tanhf_fast(cn);
                if (t < len1) { c1 = cn; h1 = hn; }
            }
            float* hn = hs + ((t + 1) & 1) * 256;
            hn[k] = h0; hn[128 + k] = h1;
        }
        __syncthreads();

        gxc0 = gxn0; gxc1 = gxn1;
    }

    if (jg == 0) {
        g_h[(b0 + 0) * HH + k] = h0;
        g_h[(b0 + 1) * HH + k] = h1;
    }
}

// ======================================================================
// Kernel 3: out[b][c] = h[b] . fc_w[c] + fc_b[c]   (256 x 6)
// ======================================================================
__global__ void __launch_bounds__(256) fc_kernel(
    const float* __restrict__ fc_w,
    const float* __restrict__ fc_b,
    float* __restrict__ out)
{
    __shared__ float wsm[CC * HH];
    __shared__ float bsm2[CC];
    int tid = threadIdx.x;
    for (int i = tid; i < CC * HH; i += 256) wsm[i] = fc_w[i];
    if (tid < CC) bsm2[tid] = fc_b[tid];
    __syncthreads();

    float s[CC];
#pragma unroll
    for (int c = 0; c < CC; ++c) s[c] = bsm2[c];
    const float* h = g_h + tid * HH;
#pragma unroll 8
    for (int kk = 0; kk < HH; ++kk) {
        float hk = h[kk];
#pragma unroll
        for (int c = 0; c < CC; ++c) s[c] += hk * wsm[c * HH + kk];
    }
#pragma unroll
    for (int c = 0; c < CC; ++c) out[tid * CC + c] = s[c];
}

// ======================================================================
extern "C" void kernel_launch(void* const* d_in, const int* in_sizes, int n_in,
                              void* d_out, int out_size)
{
    const float* x     = (const float*)d_in[0];
    const float* W_ih  = (const float*)d_in[1];
    const float* W_hh  = (const float*)d_in[2];
    const float* b_ih  = (const float*)d_in[3];
    const float* b_hh  = (const float*)d_in[4];
    const float* fc_w  = (const float*)d_in[5];
    const float* fc_b  = (const float*)d_in[6];
    const int*   lens  = (const int*)d_in[7];
    float* out = (float*)d_out;

    cudaFuncSetAttribute(gx_kernel, cudaFuncAttributeMaxDynamicSharedMemorySize, SMEM_GX);
    cudaFuncSetAttribute(lstm_kernel, cudaFuncAttributeMaxDynamicSharedMemorySize, SMEM_LS);

    size_t total = NXP + NWP;
    int pblocks = (int)((total + 255) / 256);
    precvt_kernel<<<pblocks, 256>>>(x, W_ih);

    dim3 g1((TT * BB) / 128, G4 / 128);   // 1024 x 4
    gx_kernel<<<g1, 256, SMEM_GX>>>(b_ih, b_hh);

    lstm_kernel<<<BB / 2, 512, SMEM_LS>>>(W_hh, lens);

    fc_kernel<<<1, 256>>>(fc_w, fc_b, out);
}

// round 16
// speedup vs baseline: 2.1684x; 1.0859x over previous
#include <cuda_runtime.h>
#include <cuda_bf16.h>
#include <cstdint>

typedef unsigned long long ull;

// Problem constants
#define BB   256
#define TT   512
#define DD   300
#define HH   128
#define G4   512          // 4*H
#define CC   6
#define KP   320          // K padded

// ---------------- scratch (device globals: allocation-free) ----------------
__device__ float g_gx[(size_t)TT * BB * G4];                 // [t][b][g]
__device__ float g_h[BB * HH];                               // final hidden
// g_xhi/g_xlo stored in M-ORDER: row m = t*BB + b (matches g_gx)
__device__ __nv_bfloat16 g_xhi[(size_t)BB * TT * KP];
__device__ __nv_bfloat16 g_xlo[(size_t)BB * TT * KP];
__device__ __nv_bfloat16 g_whi[(size_t)G4 * KP];
__device__ __nv_bfloat16 g_wlo[(size_t)G4 * KP];

// ---------------- helpers ----------------
__device__ __forceinline__ ull fma2(ull a, ull b, ull c) {
    ull d;
    asm("fma.rn.f32x2 %0, %1, %2, %3;" : "=l"(d) : "l"(a), "l"(b), "l"(c));
    return d;
}
__device__ __forceinline__ ull pack2(float lo, float hi) {
    ull r;
    asm("mov.b64 %0, {%1, %2};" : "=l"(r) : "f"(lo), "f"(hi));
    return r;
}
__device__ __forceinline__ float sum2(ull v) {
    float lo, hi;
    asm("mov.b64 {%0, %1}, %2;" : "=f"(lo), "=f"(hi) : "l"(v));
    return lo + hi;
}
__device__ __forceinline__ float sigf(float x) { return 1.f / (1.f + __expf(-x)); }
__device__ __forceinline__ float tanhf_fast(float x) {
    float e = __expf(-2.f * fabsf(x));
    float r = (1.f - e) / (1.f + e);
    return copysignf(r, x);
}
__device__ __forceinline__ void cp16(void* smem_dst, const void* gsrc) {
    uint32_t sa = (uint32_t)__cvta_generic_to_shared(smem_dst);
    asm volatile("cp.async.cg.shared.global [%0], [%1], 16;\n" :: "r"(sa), "l"(gsrc));
}
__device__ __forceinline__ void cp_commit() { asm volatile("cp.async.commit_group;\n" ::: "memory"); }

// m16n8k16 bf16 mma, fp32 accum
__device__ __forceinline__ void mma16816(float* c, const uint32_t* a,
                                         uint32_t b0, uint32_t b1) {
    asm volatile(
        "mma.sync.aligned.m16n8k16.row.col.f32.bf16.bf16.f32 "
        "{%0,%1,%2,%3}, {%4,%5,%6,%7}, {%8,%9}, {%0,%1,%2,%3};"
        : "+f"(c[0]), "+f"(c[1]), "+f"(c[2]), "+f"(c[3])
        : "r"(a[0]), "r"(a[1]), "r"(a[2]), "r"(a[3]), "r"(b0), "r"(b1));
}

// ======================================================================
// Kernel 0: fp32 -> bf16 hi/lo precompute, zero-pad K to 320.
// x rows transposed to m-order: m = t*BB + b.
// ======================================================================
#define NXP ((size_t)BB * TT * (KP/2))
#define NWP ((size_t)G4 * (KP/2))

__global__ void __launch_bounds__(256) precvt_kernel(
    const float* __restrict__ x,
    const float* __restrict__ W_ih)
{
    size_t idx = (size_t)blockIdx.x * 256 + threadIdx.x;
    size_t total = NXP + NWP;
    if (idx >= total) return;

    const float* src;
    __nv_bfloat16 *dhi, *dlo;
    size_t kp;
    if (idx < NXP) {
        size_t row_lin = idx / (KP/2);
        kp = idx % (KP/2);
        size_t b = row_lin / TT;
        size_t t = row_lin % TT;
        size_t m = t * BB + b;
        src = x + row_lin * DD;
        dhi = g_xhi + m * KP; dlo = g_xlo + m * KP;
    } else {
        size_t j = idx - NXP;
        size_t row = j / (KP/2);
        kp = j % (KP/2);
        src = W_ih + row * DD;
        dhi = g_whi + row * KP; dlo = g_wlo + row * KP;
    }
    int kg = (int)kp * 2;
    float2 v = (kg < DD) ? *reinterpret_cast<const float2*>(src + kg) : make_float2(0.f, 0.f);
    __nv_bfloat16 h0 = __float2bfloat16(v.x);
    __nv_bfloat16 h1 = __float2bfloat16(v.y);
    __nv_bfloat16 l0 = __float2bfloat16(v.x - __bfloat162float(h0));
    __nv_bfloat16 l1 = __float2bfloat16(v.y - __bfloat162float(h1));
    uint32_t ph = (uint32_t)__bfloat16_as_ushort(h0) | ((uint32_t)__bfloat16_as_ushort(h1) << 16);
    uint32_t pl = (uint32_t)__bfloat16_as_ushort(l0) | ((uint32_t)__bfloat16_as_ushort(l1) << 16);
    *reinterpret_cast<uint32_t*>(dhi + kg) = ph;
    *reinterpret_cast<uint32_t*>(dlo + kg) = pl;
}

// ======================================================================
// Kernel 1: gx HMMA GEMM (unchanged core). GRID IS NOW (N_tiles, M_tiles):
// consecutive block ids = the 4 N-tiles of one M-tile -> A tiles hit L2.
// ======================================================================
#define SSTR   40
#define ARR_B  (128 * SSTR * 2)
#define BUF_B  (4 * ARR_B)
#define SMEM_GX (2 * BUF_B + 512)

__global__ void __launch_bounds__(256, 2) gx_kernel(
    const float* __restrict__ b_ih,
    const float* __restrict__ b_hh)
{
    extern __shared__ char sm[];
    float* bsm = reinterpret_cast<float*>(sm + 2 * BUF_B);

    const int tid  = threadIdx.x;
    const int wid  = tid >> 5;
    const int lane = tid & 31;
    const int g    = lane >> 2;
    const int t4   = lane & 3;

    const int wr = wid & 3;
    const int wc = wid >> 2;

    const int n0  = blockIdx.x * 128;    // N is x (fast) dim now
    const int m0  = blockIdx.y * 128;

    if (tid < 128) bsm[tid] = b_ih[n0 + tid] + b_hh[n0 + tid];

    float acc[2][8][4];
#pragma unroll
    for (int mt = 0; mt < 2; ++mt)
#pragma unroll
        for (int nt = 0; nt < 8; ++nt)
#pragma unroll
            for (int r = 0; r < 4; ++r) acc[mt][nt][r] = 0.f;

    auto issue_slab = [&](int s, int buf) {
        char* base = sm + buf * BUF_B;
#pragma unroll
        for (int it = 0; it < 8; ++it) {
            int i   = it * 256 + tid;
            int arr = i >> 9;
            int r   = (i >> 2) & 127;
            int c   = i & 3;
            const __nv_bfloat16* gsrc;
            if (arr == 0)      gsrc = g_xhi + (size_t)(m0 + r) * KP;
            else if (arr == 1) gsrc = g_xlo + (size_t)(m0 + r) * KP;
            else if (arr == 2) gsrc = g_whi + (size_t)(n0 + r) * KP;
            else               gsrc = g_wlo + (size_t)(n0 + r) * KP;
            cp16(base + arr * ARR_B + (r * SSTR + c * 8) * 2,
                 reinterpret_cast<const char*>(gsrc) + s * 64 + c * 16);
        }
        cp_commit();
    };

    issue_slab(0, 0);

    for (int s = 0; s < 10; ++s) {
        if (s + 1 < 10) issue_slab(s + 1, (s + 1) & 1);
        if (s + 1 < 10) { asm volatile("cp.async.wait_group 1;\n" ::: "memory"); }
        else            { asm volatile("cp.async.wait_group 0;\n" ::: "memory"); }
        __syncthreads();

        char* base = sm + (s & 1) * BUF_B;
        __nv_bfloat16* Ahi = reinterpret_cast<__nv_bfloat16*>(base);
        __nv_bfloat16* Alo = reinterpret_cast<__nv_bfloat16*>(base + ARR_B);
        __nv_bfloat16* Bhi = reinterpret_cast<__nv_bfloat16*>(base + 2 * ARR_B);
        __nv_bfloat16* Blo = reinterpret_cast<__nv_bfloat16*>(base + 3 * ARR_B);

#pragma unroll
        for (int ks = 0; ks < 2; ++ks) {
            const int kb = ks * 16;
            uint32_t ahf[2][4], alf[2][4];
#pragma unroll
            for (int mt = 0; mt < 2; ++mt) {
                int r0 = (wr * 32 + mt * 16 + g) * SSTR + kb + t4 * 2;
                int r1 = r0 + 8 * SSTR;
                ahf[mt][0] = *reinterpret_cast<const uint32_t*>(&Ahi[r0]);
                ahf[mt][1] = *reinterpret_cast<const uint32_t*>(&Ahi[r1]);
                ahf[mt][2] = *reinterpret_cast<const uint32_t*>(&Ahi[r0 + 8]);
                ahf[mt][3] = *reinterpret_cast<const uint32_t*>(&Ahi[r1 + 8]);
                alf[mt][0] = *reinterpret_cast<const uint32_t*>(&Alo[r0]);
                alf[mt][1] = *reinterpret_cast<const uint32_t*>(&Alo[r1]);
                alf[mt][2] = *reinterpret_cast<const uint32_t*>(&Alo[r0 + 8]);
                alf[mt][3] = *reinterpret_cast<const uint32_t*>(&Alo[r1 + 8]);
            }
#pragma unroll
            for (int nt = 0; nt < 8; ++nt) {
                int br = (wc * 64 + nt * 8 + g) * SSTR + kb + t4 * 2;
                uint32_t bh0 = *reinterpret_cast<const uint32_t*>(&Bhi[br]);
                uint32_t bh1 = *reinterpret_cast<const uint32_t*>(&Bhi[br + 8]);
                uint32_t bl0 = *reinterpret_cast<const uint32_t*>(&Blo[br]);
                uint32_t bl1 = *reinterpret_cast<const uint32_t*>(&Blo[br + 8]);
#pragma unroll
                for (int mt = 0; mt < 2; ++mt) {
                    mma16816(acc[mt][nt], ahf[mt], bh0, bh1);
                    mma16816(acc[mt][nt], ahf[mt], bl0, bl1);
                    mma16816(acc[mt][nt], alf[mt], bh0, bh1);
                }
            }
        }
        __syncthreads();
    }

#pragma unroll
    for (int mt = 0; mt < 2; ++mt) {
#pragma unroll
        for (int nt = 0; nt < 8; ++nt) {
            int mrow = m0 + wr * 32 + mt * 16 + g;
            int nc   = wc * 64 + nt * 8 + t4 * 2;
            float b0v = bsm[nc], b1v = bsm[nc + 1];
            float2 v0 = make_float2(acc[mt][nt][0] + b0v, acc[mt][nt][1] + b1v);
            float2 v1 = make_float2(acc[mt][nt][2] + b0v, acc[mt][nt][3] + b1v);
            *reinterpret_cast<float2*>(&g_gx[(size_t)mrow * G4 + n0 + nc]) = v0;
            *reinterpret_cast<float2*>(&g_gx[(size_t)(mrow + 8) * G4 + n0 + nc]) = v1;
        }
    }
}

// ======================================================================
// Kernel 2: persistent LSTM. 128 blocks x 2 batches, 512 threads.
// Changes vs round-4: W_i/W_f in j-QUAD layout (LDS.128, half the load
// instrs); ALL groups write partials; tail split jg0->batch0, jg1->batch1
// (2x parallel elementwise); branchless gx prefetch.
// ======================================================================
#define RSTR3    33                           // odd stride: conflict-free
#define OFF_WI4  0                            // [32 jq][128 k][4]
#define OFF_WF4  16384
#define OFF_HS3  32768                        // hs[2][2][128]
#define OFF_RED3 33280                        // red[128][33]
#define SMEM_LS  ((OFF_RED3 + 128 * RSTR3) * 4)   // 150016 B

__global__ void __launch_bounds__(512, 1) lstm_kernel(
    const float* __restrict__ W_hh,
    const int*   __restrict__ lengths)
{
    extern __shared__ float smf[];
    float* Wi4 = smf + OFF_WI4;
    float* Wf4 = smf + OFF_WF4;
    float* hs  = smf + OFF_HS3;
    float* red = smf + OFF_RED3;

    const int tid = threadIdx.x;
    const int jg  = tid >> 7;          // 0..3
    const int k   = tid & 127;
    const int jb  = jg * 32;           // j window base
    const int jbq = jg * 8;            // j-quad window base
    const int b0  = blockIdx.x * 2;

    // stage quad-layout W for gates i, f: Wi4[(jq*128 + k)*4 + c] = W[k][4jq+c]
    for (int idx = tid; idx < 4096; idx += 512) {
        int jq = idx >> 7;
        int kk = idx & 127;
        float4 vi = *reinterpret_cast<const float4*>(&W_hh[(size_t)kk * HH + jq * 4]);
        float4 vf = *reinterpret_cast<const float4*>(&W_hh[(size_t)(HH + kk) * HH + jq * 4]);
        *reinterpret_cast<float4*>(&Wi4[(jq * 128 + kk) * 4]) = vi;
        *reinterpret_cast<float4*>(&Wf4[(jq * 128 + kk) * 4]) = vf;
    }

    // register pairs for gates g, o on own j-window
    ull wg2[16], wo2[16];
    {
        const float* gp = &W_hh[(size_t)(2*HH + k) * HH + jb];
        const float* op = &W_hh[(size_t)(3*HH + k) * HH + jb];
#pragma unroll
        for (int m = 0; m < 8; ++m) {
            ulonglong2 a = *reinterpret_cast<const ulonglong2*>(gp + m*4);
            wg2[m*2] = a.x; wg2[m*2+1] = a.y;
            ulonglong2 b = *reinterpret_cast<const ulonglong2*>(op + m*4);
            wo2[m*2] = b.x; wo2[m*2+1] = b.y;
        }
    }

    // per-thread recurrent state: jg0 owns batch0, jg1 owns batch1
    const int mylen = (jg < 2) ? lengths[b0 + jg] : 0;
    float cme = 0.f, hme = 0.f;

    if (jg == 0) { hs[k] = 0.f; hs[128+k] = 0.f; hs[256+k] = 0.f; hs[384+k] = 0.f; }
    __syncthreads();

    float gxc0, gxc1;
    {
        const float* r = g_gx + (size_t)b0 * G4;
        gxc0 = r[jg*HH + k];
        gxc1 = r[G4 + jg*HH + k];
    }

    for (int t = 0; t < TT; ++t) {
        // branchless prefetch of next step's gx
        int tn = (t + 1 < TT) ? (t + 1) : t;
        const float* rg = g_gx + (size_t)(tn * BB + b0) * G4;
        float gxn0 = rg[jg*HH + k];
        float gxn1 = rg[G4 + jg*HH + k];

        ull acc[4][2];
#pragma unroll
        for (int gi = 0; gi < 4; ++gi) {
            acc[gi][0] = pack2((gi == jg) ? gxc0 : 0.f, 0.f);
            acc[gi][1] = pack2((gi == jg) ? gxc1 : 0.f, 0.f);
        }

        const float* hb = hs + (t & 1) * 256;
        const ulonglong2* h0p = reinterpret_cast<const ulonglong2*>(hb + jb);
        const ulonglong2* h1p = reinterpret_cast<const ulonglong2*>(hb + 128 + jb);

#pragma unroll
        for (int q = 0; q < 8; ++q) {
            ulonglong2 hp0 = h0p[q];
            ulonglong2 hp1 = h1p[q];
            ulonglong2 wi = *reinterpret_cast<const ulonglong2*>(&Wi4[((jbq + q) * 128 + k) * 4]);
            ulonglong2 wf = *reinterpret_cast<const ulonglong2*>(&Wf4[((jbq + q) * 128 + k) * 4]);

            acc[0][0] = fma2(wi.x, hp0.x, acc[0][0]);
            acc[0][0] = fma2(wi.y, hp0.y, acc[0][0]);
            acc[0][1] = fma2(wi.x, hp1.x, acc[0][1]);
            acc[0][1] = fma2(wi.y, hp1.y, acc[0][1]);

            acc[1][0] = fma2(wf.x, hp0.x, acc[1][0]);
            acc[1][0] = fma2(wf.y, hp0.y, acc[1][0]);
            acc[1][1] = fma2(wf.x, hp1.x, acc[1][1]);
            acc[1][1] = fma2(wf.y, hp1.y, acc[1][1]);

            acc[2][0] = fma2(wg2[2*q],   hp0.x, acc[2][0]);
            acc[2][0] = fma2(wg2[2*q+1], hp0.y, acc[2][0]);
            acc[2][1] = fma2(wg2[2*q],   hp1.x, acc[2][1]);
            acc[2][1] = fma2(wg2[2*q+1], hp1.y, acc[2][1]);

            acc[3][0] = fma2(wo2[2*q],   hp0.x, acc[3][0]);
            acc[3][0] = fma2(wo2[2*q+1], hp0.y, acc[3][0]);
            acc[3][1] = fma2(wo2[2*q],   hp1.x, acc[3][1]);
            acc[3][1] = fma2(wo2[2*q+1], hp1.y, acc[3][1]);
        }

        // all groups write 8 partials: layout red[k][jg*8 + gi*2 + bi]
        {
            float* r = &red[k * RSTR3 + jg * 8];
            r[0] = sum2(acc[0][0]); r[1] = sum2(acc[0][1]);
            r[2] = sum2(acc[1][0]); r[3] = sum2(acc[1][1]);
            r[4] = sum2(acc[2][0]); r[5] = sum2(acc[2][1]);
            r[6] = sum2(acc[3][0]); r[7] = sum2(acc[3][1]);
        }
        __syncthreads();

        // tail: jg0 -> batch0, jg1 -> batch1 (parallel)
        if (jg < 2) {
            const float* r = &red[k * RSTR3 + jg];   // + gi*2 below, bi folded in
            float sg0 = r[0]  + r[8]  + r[16] + r[24];
            float sg1 = r[2]  + r[10] + r[18] + r[26];
            float sg2 = r[4]  + r[12] + r[20] + r[28];
            float sg3 = r[6]  + r[14] + r[22] + r[30];

            float ig = sigf(sg0), fg = sigf(sg1);
            float gg = tanhf_fast(sg2), og = sigf(sg3);
            float cn = fg * cme + ig * gg;
            float hn = og * tanhf_fast(cn);
            if (t < mylen) { cme = cn; hme = hn; }
            hs[((t + 1) & 1) * 256 + jg * 128 + k] = hme;
        }
        __syncthreads();

        gxc0 = gxn0; gxc1 = gxn1;
    }

    if (jg < 2) g_h[(b0 + jg) * HH + k] = hme;
}

// ======================================================================
// Kernel 3: fc -- warp per batch, coalesced h reads, shfl reduction.
// 32 blocks x 256 threads (8 warps) = 256 warps = 256 batches.
// ======================================================================
__global__ void __launch_bounds__(256) fc_kernel(
    const float* __restrict__ fc_w,
    const float* __restrict__ fc_b,
    float* __restrict__ out)
{
    __shared__ float wsm[CC * HH];
    __shared__ float bsm2[CC];
    int tid = threadIdx.x;
    for (int i = tid; i < CC * HH; i += 256) wsm[i] = fc_w[i];
    if (tid < CC) bsm2[tid] = fc_b[tid];
    __syncthreads();

    const int w    = tid >> 5;
    const int lane = tid & 31;
    const int b    = blockIdx.x * 8 + w;

    float4 hv = *reinterpret_cast<const float4*>(&g_h[b * HH + lane * 4]);

    float s[CC];
#pragma unroll
    for (int c = 0; c < CC; ++c) {
        const float* wr = &wsm[c * HH + lane * 4];
        s[c] = hv.x * wr[0] + hv.y * wr[1] + hv.z * wr[2] + hv.w * wr[3];
#pragma unroll
        for (int off = 16; off > 0; off >>= 1)
            s[c] += __shfl_xor_sync(0xFFFFFFFF, s[c], off);
    }
    if (lane == 0) {
#pragma unroll
        for (int c = 0; c < CC; ++c)
            out[b * CC + c] = s[c] + bsm2[c];
    }
}

// ======================================================================
extern "C" void kernel_launch(void* const* d_in, const int* in_sizes, int n_in,
                              void* d_out, int out_size)
{
    const float* x     = (const float*)d_in[0];
    const float* W_ih  = (const float*)d_in[1];
    const float* W_hh  = (const float*)d_in[2];
    const float* b_ih  = (const float*)d_in[3];
    const float* b_hh  = (const float*)d_in[4];
    const float* fc_w  = (const float*)d_in[5];
    const float* fc_b  = (const float*)d_in[6];
    const int*   lens  = (const int*)d_in[7];
    float* out = (float*)d_out;

    cudaFuncSetAttribute(gx_kernel, cudaFuncAttributeMaxDynamicSharedMemorySize, SMEM_GX);
    cudaFuncSetAttribute(lstm_kernel, cudaFuncAttributeMaxDynamicSharedMemorySize, SMEM_LS);

    size_t total = NXP + NWP;
    int pblocks = (int)((total + 255) / 256);
    precvt_kernel<<<pblocks, 256>>>(x, W_ih);

    dim3 g1(G4 / 128, (TT * BB) / 128);   // (4, 1024): N fast -> A-tile L2 reuse
    gx_kernel<<<g1, 256, SMEM_GX>>>(b_ih, b_hh);

    lstm_kernel<<<BB / 2, 512, SMEM_LS>>>(W_hh, lens);

    fc_kernel<<<32, 256>>>(fc_w, fc_b, out);
}